// round 14
// baseline (speedup 1.0000x reference)
#include <cuda_runtime.h>
#include <cuda_fp16.h>
#include <math.h>
#include <stdint.h>

// ---------------- problem constants ----------------
#define NROWS 8192     // B*T
#define DDIM  1024
#define EDIM  2048
#define CDDIM 256
#define NCODE 1024

// output layout (fp32 concat in reference return order)
#define OFF_Q     0
#define OFF_LOSS  2097152
#define OFF_PERP  2097153
#define OFF_ENC   2097154
#define OFF_IDX   10485762

// ---------------- scratch ----------------
__device__ uint32_t g_Sh[(size_t)2 * NROWS * (DDIM / 2)];      // states|next rows
__device__ uint32_t g_Sl[(size_t)2 * NROWS * (DDIM / 2)];
__device__ uint32_t g_Wsh[(size_t)EDIM * (DDIM / 2)];          // W_s^T  [E][D]
__device__ uint32_t g_Wsl[(size_t)EDIM * (DDIM / 2)];
__device__ uint32_t g_Wph[(size_t)CDDIM * (2 * EDIM / 2)];     // W_p^T  [CD][2E]
__device__ uint32_t g_Wpl[(size_t)CDDIM * (2 * EDIM / 2)];
__device__ uint32_t g_Hh[(size_t)NROWS * (2 * EDIM / 2)];      // H  [M][4096]
__device__ uint32_t g_Hl[(size_t)NROWS * (2 * EDIM / 2)];
__device__ uint32_t g_Lh[(size_t)NROWS * (CDDIM / 2)];         // latent fp16 h/l
__device__ uint32_t g_Ll[(size_t)NROWS * (CDDIM / 2)];
__device__ uint32_t g_Ch[(size_t)NCODE * (CDDIM / 2)];         // codebook fp16 h/l
__device__ uint32_t g_Cl[(size_t)NCODE * (CDDIM / 2)];

__device__ float g_cnorm[NCODE];
__device__ float g_pval[(size_t)NROWS * 32];
__device__ int   g_pidx[(size_t)NROWS * 32];
__device__ int   g_counts[NCODE];
__device__ float g_loss_sum;

// ---------------- helpers ----------------
__device__ __forceinline__ uint32_t smem_u32(const void* p) {
    uint32_t a;
    asm("{ .reg .u64 t; cvta.to.shared.u64 t, %1; cvt.u32.u64 %0, t; }" : "=r"(a) : "l"(p));
    return a;
}

#define CP16(dst, src) \
    asm volatile("cp.async.cg.shared.global [%0], [%1], 16;" :: "r"(dst), "l"(src))
#define CP_COMMIT() asm volatile("cp.async.commit_group;" ::: "memory")
template <int N>
__device__ __forceinline__ void cp_wait() {
    asm volatile("cp.async.wait_group %0;" :: "n"(N) : "memory");
}

__device__ __forceinline__ void ldm_x4(uint32_t* r, uint32_t addr) {
    asm volatile("ldmatrix.sync.aligned.m8n8.x4.shared.b16 {%0,%1,%2,%3}, [%4];"
                 : "=r"(r[0]), "=r"(r[1]), "=r"(r[2]), "=r"(r[3]) : "r"(addr));
}

// fp16 hi/lo split of an fp32 value
__device__ __forceinline__ void split_h(float v, uint16_t& h, uint16_t& l) {
    __half hh = __float2half_rn(v);
    float r = v - __half2float(hh);
    h = __half_as_ushort(hh);
    l = __half_as_ushort(__float2half_rn(r));
}

// fp16 mma: D += A*B, m16n8k16, fp32 accumulate
__device__ __forceinline__ void mma16(float* c, const uint32_t* a, const uint32_t* b) {
    asm volatile(
        "mma.sync.aligned.m16n8k16.row.col.f32.f16.f16.f32 "
        "{%0,%1,%2,%3}, {%4,%5,%6,%7}, {%8,%9}, {%0,%1,%2,%3};"
        : "+f"(c[0]), "+f"(c[1]), "+f"(c[2]), "+f"(c[3])
        : "r"(a[0]), "r"(a[1]), "r"(a[2]), "r"(a[3]), "r"(b[0]), "r"(b[1]));
}

__device__ __forceinline__ float gelu_tanh(float x) {
    float x3 = x * x * x;
    float t  = tanhf(0.7978845608028654f * (x + 0.044715f * x3));
    return 0.5f * x * (1.0f + t);
}

// ---------------- fused preprocessing kernel ----------------
#define PRE_BLOCKS 36356

__global__ void k_pre(const float* __restrict__ states,
                      const float* __restrict__ next_states,
                      const float* __restrict__ W_s,
                      const float* __restrict__ W_p,
                      const float* __restrict__ cb) {
    const int b = blockIdx.x;
    const int tid = threadIdx.x;

    if (b < 32768) {
        const int which = b >> 14;
        const int bb = b & 16383;
        const float* src = which ? next_states : states;
        const uint32_t off = which ? (uint32_t)(NROWS * DDIM / 2) : 0u;
        int i = bb * 256 + tid;
        float2 v = ((const float2*)src)[i];
        uint16_t h0, l0, h1, l1;
        split_h(v.x, h0, l0);
        split_h(v.y, h1, l1);
        g_Sh[off + i] = (uint32_t)h0 | ((uint32_t)h1 << 16);
        g_Sl[off + i] = (uint32_t)l0 | ((uint32_t)l1 << 16);
    } else if (b < 35840) {
        const int which = (b >= 34816);
        const int bb = which ? (b - 34816) : (b - 32768);
        const int K = which ? (2 * EDIM) : DDIM;
        const int N = which ? CDDIM : EDIM;
        const int nblk = N / 32;
        const int n0 = (bb % nblk) * 32, k0 = (bb / nblk) * 32;
        const float* src = which ? W_p : W_s;
        __half* dh = (__half*)(which ? g_Wph : g_Wsh);
        __half* dl = (__half*)(which ? g_Wpl : g_Wsl);

        __shared__ float ts[32][33];
        const int tx = tid & 31, ty = tid >> 5;
        #pragma unroll
        for (int r = 0; r < 4; r++)
            ts[ty + 8 * r][tx] = src[(size_t)(k0 + ty + 8 * r) * N + n0 + tx];
        __syncthreads();
        #pragma unroll
        for (int r = 0; r < 4; r++) {
            int n = n0 + ty + 8 * r, k = k0 + tx;
            float v = ts[tx][ty + 8 * r];
            uint16_t h, l;
            split_h(v, h, l);
            dh[(size_t)n * K + k] = __ushort_as_half(h);
            dl[(size_t)n * K + k] = __ushort_as_half(l);
        }
    } else if (b < 36352) {
        int i = (b - 35840) * 256 + tid;
        float2 v = ((const float2*)cb)[i];
        uint16_t h0, l0, h1, l1;
        split_h(v.x, h0, l0);
        split_h(v.y, h1, l1);
        g_Ch[i] = (uint32_t)h0 | ((uint32_t)h1 << 16);
        g_Cl[i] = (uint32_t)l0 | ((uint32_t)l1 << 16);
    } else {
        int c = (b - 36352) * 256 + tid;
        if (c < NCODE) {
            g_counts[c] = 0;
            float s = 0.0f;
            const float* row = cb + (size_t)c * CDDIM;
            #pragma unroll 8
            for (int k = 0; k < CDDIM; k++) { float v = row[k]; s += v * v; }
            g_cnorm[c] = s;
        }
        if (c == 0) g_loss_sum = 0.0f;
    }
}

// ---------------- BIG-M fp16 split GEMM (enc + score) ----------------
// CTA 256(M) x 128(N), 512 thr, 16 warps 4m x 4n, warp tile 64x32, NSTG=3.
// 1 CTA/SM (128-reg cap, 64K regs = full RF), 16 warps/SM — same per-warp
// inner loop as the proven R12 kernel, double the A reuse.
template <int MODE, int KT>
__global__ void __launch_bounds__(512, 1) gemm_big(const float* __restrict__ bias) {
    extern __shared__ uint32_t smu[];
    constexpr int KW   = KT / 2;
    constexpr int NCH  = KT / 32;
    constexpr int ASZ  = 256 * 32;            // words
    constexpr int BSZ  = 128 * 32;
    constexpr int STG  = ASZ + BSZ;           // 12288 words = 48KB
    constexpr int NSTG = 3;

    const uint32_t* Ah = (MODE == 0) ? g_Sh : g_Lh;
    const uint32_t* Al = (MODE == 0) ? g_Sl : g_Ll;
    const uint32_t* Bh = (MODE == 0) ? g_Wsh : g_Ch;
    const uint32_t* Bl = (MODE == 0) ? g_Wsl : g_Cl;

    const int tid = threadIdx.x;
    const int wid = tid >> 5, lane = tid & 31;
    const int wm  = (wid & 3) * 64;
    const int wn  = (wid >> 2) * 32;
    const int lt  = lane & 3, lg = lane >> 2;

    const int m0 = blockIdx.y * 256, n0 = blockIdx.x * 128;
    const size_t arow0 = (MODE == 0) ? ((size_t)blockIdx.z * NROWS + m0) : (size_t)m0;
    const uint32_t sb = smem_u32(smu);

    const int l7 = lane & 7;
    const int amrow0 = wm + l7 + 8 * ((lane >> 3) & 1);      // + 16*mt
    const uint32_t axk = ((lane >> 4) & 1) ^ l7;
    const int bnrow0 = wn + l7 + 8 * ((lane >> 4) & 1);      // + 16*p
    const uint32_t bxk = ((lane >> 3) & 1) ^ l7;

    float acc[4][4][4];
    #pragma unroll
    for (int i = 0; i < 4; i++)
        #pragma unroll
        for (int j = 0; j < 4; j++)
            #pragma unroll
            for (int e = 0; e < 4; e++) acc[i][j][e] = 0.0f;

    auto copy_chunk = [&](int c, int stg) {
        const uint32_t dA = sb + stg * STG * 4;
        const uint32_t dB = dA + ASZ * 4;
        // A: 256 rows x 8 parts = 2048 units -> 4/thread
        #pragma unroll
        for (int j = 0; j < 4; j++) {
            int u = tid + j * 512;
            int m = u >> 3, p = u & 7;
            const uint32_t* s = ((p < 4) ? Ah : Al)
                + (arow0 + m) * KW + c * 16 + (p & 3) * 4;
            uint32_t dst = dA + (m * 32 + ((p ^ (m & 7)) << 2)) * 4;
            CP16(dst, s);
        }
        // B: 128 rows x 8 parts = 1024 units -> 2/thread
        #pragma unroll
        for (int j = 0; j < 2; j++) {
            int u = tid + j * 512;
            int n = u >> 3, p = u & 7;
            const uint32_t* s = ((p < 4) ? Bh : Bl)
                + (size_t)(n0 + n) * KW + c * 16 + (p & 3) * 4;
            uint32_t dst = dB + (n * 32 + ((p ^ (n & 7)) << 2)) * 4;
            CP16(dst, s);
        }
    };

    auto compute = [&](int stg) {
        const uint32_t sA = sb + stg * STG * 4;
        const uint32_t sB = sA + ASZ * 4;
        #pragma unroll
        for (int s = 0; s < 2; s++) {
            const uint32_t ch = 2 * s;
            const uint32_t cl = 2 * s + 4;
            // B resident for this slab: 2 pairs x (hi, lo)
            uint32_t bh[2][4], bl[2][4];
            #pragma unroll
            for (int p = 0; p < 2; p++) {
                const uint32_t bb = sB + (bnrow0 + 16 * p) * 128;
                ldm_x4(bh[p], bb + ((ch ^ bxk) << 4));
                ldm_x4(bl[p], bb + ((cl ^ bxk) << 4));
            }
            // stream A per mt; product-major issue within mt
            #pragma unroll
            for (int mt = 0; mt < 4; mt++) {
                uint32_t ah[4], al[4];
                const uint32_t ab = sA + (amrow0 + 16 * mt) * 128;
                ldm_x4(ah, ab + ((ch ^ axk) << 4));
                ldm_x4(al, ab + ((cl ^ axk) << 4));
                // hh
                mma16(acc[mt][0], ah, bh[0]);
                mma16(acc[mt][1], ah, bh[0] + 2);
                mma16(acc[mt][2], ah, bh[1]);
                mma16(acc[mt][3], ah, bh[1] + 2);
                // hl
                mma16(acc[mt][0], ah, bl[0]);
                mma16(acc[mt][1], ah, bl[0] + 2);
                mma16(acc[mt][2], ah, bl[1]);
                mma16(acc[mt][3], ah, bl[1] + 2);
                // lh
                mma16(acc[mt][0], al, bh[0]);
                mma16(acc[mt][1], al, bh[0] + 2);
                mma16(acc[mt][2], al, bh[1]);
                mma16(acc[mt][3], al, bh[1] + 2);
            }
        }
    };

    // ---- prologue ----
    #pragma unroll
    for (int c = 0; c < NSTG - 1 && c < NCH; c++) { copy_chunk(c, c); CP_COMMIT(); }

    // ---- mainloop ----
    int stg_c = 0, stg_n = NSTG - 1;
    for (int c = 0; c < NCH; c++) {
        cp_wait<NSTG - 2>();
        __syncthreads();
        const int cn = c + NSTG - 1;
        if (cn < NCH) copy_chunk(cn, stg_n);
        CP_COMMIT();
        compute(stg_c);
        stg_c = (stg_c + 1 == NSTG) ? 0 : stg_c + 1;
        stg_n = (stg_n + 1 == NSTG) ? 0 : stg_n + 1;
    }

    // ---- epilogue ----
    if (MODE == 0) {
        const int zoff = blockIdx.z ? EDIM : 0;
        #pragma unroll
        for (int mt = 0; mt < 4; mt++)
            #pragma unroll
            for (int h = 0; h < 2; h++) {
                const int row = m0 + wm + mt * 16 + lg + h * 8;
                #pragma unroll
                for (int nt = 0; nt < 4; nt++) {
                    const int col = wn + nt * 8 + 2 * lt;
                    float g0 = gelu_tanh(acc[mt][nt][h * 2 + 0] + bias[n0 + col]);
                    float g1 = gelu_tanh(acc[mt][nt][h * 2 + 1] + bias[n0 + col + 1]);
                    uint16_t h0, l0, h1, l1;
                    split_h(g0, h0, l0);
                    split_h(g1, h1, l1);
                    size_t cw = (size_t)row * (2 * EDIM / 2) + ((zoff + n0 + col) >> 1);
                    g_Hh[cw] = (uint32_t)h0 | ((uint32_t)h1 << 16);
                    g_Hl[cw] = (uint32_t)l0 | ((uint32_t)l1 << 16);
                }
            }
    } else {
        #pragma unroll
        for (int mt = 0; mt < 4; mt++)
            #pragma unroll
            for (int h = 0; h < 2; h++) {
                const int row = m0 + wm + mt * 16 + lg + h * 8;
                float best = INFINITY; int bi = 0;
                #pragma unroll
                for (int nt = 0; nt < 4; nt++)
                    #pragma unroll
                    for (int e = 0; e < 2; e++) {
                        const int col = n0 + wn + nt * 8 + 2 * lt + e;
                        float s = g_cnorm[col] - 2.0f * acc[mt][nt][h * 2 + e];
                        if (s < best) { best = s; bi = col; }
                    }
                #pragma unroll
                for (int msk = 1; msk <= 2; msk <<= 1) {
                    float ov = __shfl_xor_sync(0xffffffffu, best, msk);
                    int   oi = __shfl_xor_sync(0xffffffffu, bi,   msk);
                    if (ov < best || (ov == best && oi < bi)) { best = ov; bi = oi; }
                }
                if (lt == 0) {
                    // 32 slots/row: blockIdx.x (0..7) * 4 + warp-n (0..3)
                    g_pval[(size_t)row * 32 + blockIdx.x * 4 + (wid >> 2)] = best;
                    g_pidx[(size_t)row * 32 + blockIdx.x * 4 + (wid >> 2)] = bi;
                }
            }
    }
}

// ---------------- pol GEMM ----------------
// latent(fp16 h/l only) = H @ Wp^T + b_p
// CTA 64x128, 8 warps 2m x 4n, warp 32x32, NSTG=4, 2 CTAs/SM.
__global__ void __launch_bounds__(256, 2) gemm_pol(const float* __restrict__ bias) {
    extern __shared__ uint32_t smu[];
    constexpr int KT   = 2 * EDIM;
    constexpr int KW   = KT / 2;
    constexpr int NCH  = KT / 32;
    constexpr int ASZ  = 64 * 32;
    constexpr int BSZ  = 128 * 32;
    constexpr int STG  = ASZ + BSZ;
    constexpr int NSTG = 4;

    const int tid = threadIdx.x;
    const int wid = tid >> 5, lane = tid & 31;
    const int wm  = (wid & 1) * 32;
    const int wn  = (wid >> 1) * 32;
    const int lt  = lane & 3, lg = lane >> 2;

    const int m0 = blockIdx.y * 64, n0 = blockIdx.x * 128;
    const uint32_t sb = smem_u32(smu);

    const int l7 = lane & 7;
    const int amrow0 = wm + l7 + 8 * ((lane >> 3) & 1);
    const uint32_t axk = ((lane >> 4) & 1) ^ l7;
    const int bnrow0 = wn + l7 + 8 * ((lane >> 4) & 1);
    const uint32_t bxk = ((lane >> 3) & 1) ^ l7;

    float acc[2][4][4];
    #pragma unroll
    for (int i = 0; i < 2; i++)
        #pragma unroll
        for (int j = 0; j < 4; j++)
            #pragma unroll
            for (int e = 0; e < 4; e++) acc[i][j][e] = 0.0f;

    auto copy_chunk = [&](int c, int stg) {
        const uint32_t dA = sb + stg * STG * 4;
        const uint32_t dB = dA + ASZ * 4;
        #pragma unroll
        for (int j = 0; j < 2; j++) {
            int u = tid + j * 256;
            int m = u >> 3, p = u & 7;
            const uint32_t* s = ((p < 4) ? g_Hh : g_Hl)
                + (size_t)(m0 + m) * KW + c * 16 + (p & 3) * 4;
            uint32_t dst = dA + (m * 32 + ((p ^ (m & 7)) << 2)) * 4;
            CP16(dst, s);
        }
        #pragma unroll
        for (int j = 0; j < 4; j++) {
            int u = tid + j * 256;
            int n = u >> 3, p = u & 7;
            const uint32_t* s = ((p < 4) ? g_Wph : g_Wpl)
                + (size_t)(n0 + n) * KW + c * 16 + (p & 3) * 4;
            uint32_t dst = dB + (n * 32 + ((p ^ (n & 7)) << 2)) * 4;
            CP16(dst, s);
        }
    };

    auto compute = [&](int stg) {
        const uint32_t sA = sb + stg * STG * 4;
        const uint32_t sB = sA + ASZ * 4;
        const uint32_t aBase0 = sA + (amrow0)      * 128;
        const uint32_t aBase1 = sA + (amrow0 + 16) * 128;
        #pragma unroll
        for (int s = 0; s < 2; s++) {
            const uint32_t ch = 2 * s;
            const uint32_t cl = 2 * s + 4;
            uint32_t ah[2][4], al[2][4];
            ldm_x4(ah[0], aBase0 + ((ch ^ axk) << 4));
            ldm_x4(al[0], aBase0 + ((cl ^ axk) << 4));
            ldm_x4(ah[1], aBase1 + ((ch ^ axk) << 4));
            ldm_x4(al[1], aBase1 + ((cl ^ axk) << 4));
            #pragma unroll
            for (int p = 0; p < 2; p++) {
                uint32_t bh[4], bl[4];
                const uint32_t bb = sB + (bnrow0 + 16 * p) * 128;
                ldm_x4(bh, bb + ((ch ^ bxk) << 4));
                ldm_x4(bl, bb + ((cl ^ bxk) << 4));
                // product-major: hh (4 accs), hl (4), lh (4)
                mma16(acc[0][2 * p],     ah[0], bh);
                mma16(acc[0][2 * p + 1], ah[0], bh + 2);
                mma16(acc[1][2 * p],     ah[1], bh);
                mma16(acc[1][2 * p + 1], ah[1], bh + 2);
                mma16(acc[0][2 * p],     ah[0], bl);
                mma16(acc[0][2 * p + 1], ah[0], bl + 2);
                mma16(acc[1][2 * p],     ah[1], bl);
                mma16(acc[1][2 * p + 1], ah[1], bl + 2);
                mma16(acc[0][2 * p],     al[0], bh);
                mma16(acc[0][2 * p + 1], al[0], bh + 2);
                mma16(acc[1][2 * p],     al[1], bh);
                mma16(acc[1][2 * p + 1], al[1], bh + 2);
            }
        }
    };

    #pragma unroll
    for (int c = 0; c < NSTG - 1 && c < NCH; c++) { copy_chunk(c, c); CP_COMMIT(); }
    for (int c = 0; c < NCH; c++) {
        cp_wait<NSTG - 2>();
        __syncthreads();
        const int cn = c + NSTG - 1;
        if (cn < NCH) copy_chunk(cn, cn & (NSTG - 1));
        CP_COMMIT();
        compute(c & (NSTG - 1));
    }

    #pragma unroll
    for (int mt = 0; mt < 2; mt++)
        #pragma unroll
        for (int h = 0; h < 2; h++) {
            const int row = m0 + wm + mt * 16 + lg + h * 8;
            #pragma unroll
            for (int nt = 0; nt < 4; nt++) {
                const int col = wn + nt * 8 + 2 * lt;
                float v0 = acc[mt][nt][h * 2 + 0] + bias[n0 + col];
                float v1 = acc[mt][nt][h * 2 + 1] + bias[n0 + col + 1];
                uint16_t h0, l0, h1, l1;
                split_h(v0, h0, l0);
                split_h(v1, h1, l1);
                size_t cw = (size_t)row * (CDDIM / 2) + ((n0 + col) >> 1);
                g_Lh[cw] = (uint32_t)h0 | ((uint32_t)h1 << 16);
                g_Ll[cw] = (uint32_t)l0 | ((uint32_t)l1 << 16);
            }
        }
}

// ---------------- finalize ----------------
__global__ __launch_bounds__(256) void k_final(const float* __restrict__ CB,
                                               float* __restrict__ out, int full) {
    const int warp = threadIdx.x >> 5, lane = threadIdx.x & 31;
    const int row = blockIdx.x * 8 + warp;

    float v = g_pval[(size_t)row * 32 + lane];
    int  ii = g_pidx[(size_t)row * 32 + lane];
    #pragma unroll
    for (int off = 16; off > 0; off >>= 1) {
        float ov = __shfl_down_sync(0xffffffffu, v, off);
        int   oi = __shfl_down_sync(0xffffffffu, ii, off);
        if (ov < v || (ov == v && oi < ii)) { v = ov; ii = oi; }
    }
    int idx = __shfl_sync(0xffffffffu, ii, 0);

    // quantize output + commitment-loss partial (latent reconstructed h+l)
    float ls = 0.0f;
    #pragma unroll
    for (int it = 0; it < 4; it++) {
        int jw = it * 32 + lane;                       // u32 word index (0..127)
        uint32_t hw = g_Lh[(size_t)row * (CDDIM / 2) + jw];
        uint32_t lw = g_Ll[(size_t)row * (CDDIM / 2) + jw];
        float l0 = __half2float(__ushort_as_half((uint16_t)(hw & 0xffff)))
                 + __half2float(__ushort_as_half((uint16_t)(lw & 0xffff)));
        float l1 = __half2float(__ushort_as_half((uint16_t)(hw >> 16)))
                 + __half2float(__ushort_as_half((uint16_t)(lw >> 16)));
        float2 c = *(const float2*)(CB + (size_t)idx * CDDIM + 2 * jw);
        *(float2*)(out + OFF_Q + (size_t)row * CDDIM + 2 * jw) = c;
        float d0 = c.x - l0, d1 = c.y - l1;
        ls += d0 * d0 + d1 * d1;
    }
    #pragma unroll
    for (int off = 16; off > 0; off >>= 1)
        ls += __shfl_down_sync(0xffffffffu, ls, off);
    if (lane == 0) {
        atomicAdd(&g_loss_sum, ls);
        atomicAdd(&g_counts[idx], 1);
    }
    if (full) {
        float* enc = out + OFF_ENC + (size_t)row * NCODE;
        for (int j = lane; j < NCODE; j += 32) enc[j] = (j == idx) ? 1.0f : 0.0f;
        if (lane == 0) out[OFF_IDX + row] = (float)idx;
    }
}

__global__ void k_scalar(float* __restrict__ out) {
    __shared__ float sh[256];
    int t = threadIdx.x;
    float e = 0.0f;
    for (int c = t; c < NCODE; c += 256) {
        float p = (float)g_counts[c] * (1.0f / (float)NROWS);
        e += p * logf(p + 1e-10f);
    }
    sh[t] = e;
    __syncthreads();
    for (int s = 128; s > 0; s >>= 1) {
        if (t < s) sh[t] += sh[t + s];
        __syncthreads();
    }
    if (t == 0) {
        out[OFF_LOSS] = 0.25f * g_loss_sum / ((float)NROWS * (float)CDDIM);
        out[OFF_PERP] = expf(-sh[0]);
    }
}

// ---------------- launch ----------------
extern "C" void kernel_launch(void* const* d_in, const int* in_sizes, int n_in,
                              void* d_out, int out_size) {
    const float* states      = (const float*)d_in[0];
    const float* next_states = (const float*)d_in[1];
    const float* W_s         = (const float*)d_in[2];
    const float* b_s         = (const float*)d_in[3];
    const float* W_p         = (const float*)d_in[4];
    const float* b_p         = (const float*)d_in[5];
    const float* codebook    = (const float*)d_in[6];
    float* out = (float*)d_out;
    int full = (out_size >= OFF_ENC) ? 1 : 0;

    // smem: big: 3 * (256*32 + 128*32) * 4 = 147456 B (1 CTA/SM, 512 thr)
    //       pol: 4 * (64*32 + 128*32) * 4 =  98304 B (2 CTAs/SM)
    constexpr int SM_BIG = 3 * (256 * 32 + 128 * 32) * 4;
    constexpr int SM_POL = 4 * (64 * 32 + 128 * 32) * 4;
    cudaFuncSetAttribute(gemm_big<0, DDIM>,
                         cudaFuncAttributeMaxDynamicSharedMemorySize, SM_BIG);
    cudaFuncSetAttribute(gemm_big<2, CDDIM>,
                         cudaFuncAttributeMaxDynamicSharedMemorySize, SM_BIG);
    cudaFuncSetAttribute(gemm_pol,
                         cudaFuncAttributeMaxDynamicSharedMemorySize, SM_POL);

    k_pre<<<PRE_BLOCKS, 256>>>(states, next_states, W_s, W_p, codebook);

    // encoder: M=8192, N=2048, K=1024 (two inputs via grid.z) -> Hh/Hl
    gemm_big<0, DDIM><<<dim3(EDIM / 128, NROWS / 256, 2), 512, SM_BIG>>>(b_s);
    // policy head: M=8192, N=256, K=4096 -> latent fp16 h/l
    gemm_pol<<<dim3(CDDIM / 128, NROWS / 64, 1), 256, SM_POL>>>(b_p);
    // scores: M=8192, N=1024 codes, K=256 (fp16 split)
    gemm_big<2, CDDIM><<<dim3(NCODE / 128, NROWS / 256, 1), 512, SM_BIG>>>(nullptr);

    k_final<<<NROWS / 8, 256>>>(codebook, out, full);
    if (full) k_scalar<<<1, 256>>>(out);
}

// round 16
// speedup vs baseline: 1.0554x; 1.0554x over previous
#include <cuda_runtime.h>
#include <cuda_fp16.h>
#include <math.h>
#include <stdint.h>

// ---------------- problem constants ----------------
#define NROWS 8192     // B*T
#define DDIM  1024
#define EDIM  2048
#define CDDIM 256
#define NCODE 1024

// output layout (fp32 concat in reference return order)
#define OFF_Q     0
#define OFF_LOSS  2097152
#define OFF_PERP  2097153
#define OFF_ENC   2097154
#define OFF_IDX   10485762

// ---------------- scratch ----------------
__device__ __align__(16) uint32_t g_Sh[(size_t)2 * NROWS * (DDIM / 2)];
__device__ __align__(16) uint32_t g_Sl[(size_t)2 * NROWS * (DDIM / 2)];
__device__ __align__(16) uint32_t g_Wsh[(size_t)EDIM * (DDIM / 2)];
__device__ __align__(16) uint32_t g_Wsl[(size_t)EDIM * (DDIM / 2)];
__device__ __align__(16) uint32_t g_Wph[(size_t)CDDIM * (2 * EDIM / 2)];
__device__ __align__(16) uint32_t g_Wpl[(size_t)CDDIM * (2 * EDIM / 2)];
__device__ __align__(16) uint32_t g_Hh[(size_t)NROWS * (2 * EDIM / 2)];
__device__ __align__(16) uint32_t g_Hl[(size_t)NROWS * (2 * EDIM / 2)];
__device__ __align__(16) uint32_t g_Lh[(size_t)NROWS * (CDDIM / 2)];
__device__ __align__(16) uint32_t g_Ll[(size_t)NROWS * (CDDIM / 2)];
__device__ __align__(16) uint32_t g_Ch[(size_t)NCODE * (CDDIM / 2)];
__device__ __align__(16) uint32_t g_Cl[(size_t)NCODE * (CDDIM / 2)];

__device__ float g_cnorm[NCODE];
__device__ unsigned long long g_best[NROWS];   // packed (score bits << 32) | idx
__device__ int   g_counts[NCODE];
__device__ float g_loss_sum;

// ---------------- helpers ----------------
__device__ __forceinline__ uint32_t smem_u32(const void* p) {
    uint32_t a;
    asm("{ .reg .u64 t; cvta.to.shared.u64 t, %1; cvt.u32.u64 %0, t; }" : "=r"(a) : "l"(p));
    return a;
}

#define CP16(dst, src) \
    asm volatile("cp.async.cg.shared.global [%0], [%1], 16;" :: "r"(dst), "l"(src))
#define CP_COMMIT() asm volatile("cp.async.commit_group;" ::: "memory")
template <int N>
__device__ __forceinline__ void cp_wait() {
    asm volatile("cp.async.wait_group %0;" :: "n"(N) : "memory");
}

__device__ __forceinline__ void ldm_x4(uint32_t* r, uint32_t addr) {
    asm volatile("ldmatrix.sync.aligned.m8n8.x4.shared.b16 {%0,%1,%2,%3}, [%4];"
                 : "=r"(r[0]), "=r"(r[1]), "=r"(r[2]), "=r"(r[3]) : "r"(addr));
}

// fp16 hi/lo split of an fp32 value
__device__ __forceinline__ void split_h(float v, uint16_t& h, uint16_t& l) {
    __half hh = __float2half_rn(v);
    float r = v - __half2float(hh);
    h = __half_as_ushort(hh);
    l = __half_as_ushort(__float2half_rn(r));
}

// order-preserving float -> uint32 (total order, min float = min uint)
__device__ __forceinline__ uint32_t ford(float s) {
    uint32_t u = __float_as_uint(s);
    return u ^ (((uint32_t)((int32_t)u >> 31)) | 0x80000000u);
}

// fp16 mma: D += A*B, m16n8k16, fp32 accumulate
__device__ __forceinline__ void mma16(float* c, const uint32_t* a, const uint32_t* b) {
    asm volatile(
        "mma.sync.aligned.m16n8k16.row.col.f32.f16.f16.f32 "
        "{%0,%1,%2,%3}, {%4,%5,%6,%7}, {%8,%9}, {%0,%1,%2,%3};"
        : "+f"(c[0]), "+f"(c[1]), "+f"(c[2]), "+f"(c[3])
        : "r"(a[0]), "r"(a[1]), "r"(a[2]), "r"(a[3]), "r"(b[0]), "r"(b[1]));
}

__device__ __forceinline__ float gelu_tanh(float x) {
    float x3 = x * x * x;
    float t  = tanhf(0.7978845608028654f * (x + 0.044715f * x3));
    return 0.5f * x * (1.0f + t);
}

// ---------------- fused preprocessing kernel ----------------
// block ranges:
//   [0, 16384)        split states|next (float4)  -> g_Sh/g_Sl   (8192 each)
//   [16384, 18432)    transpose W_s  (64 nblk x 32 kblk = 2048)  -> g_Wsh/g_Wsl
//   [18432, 19456)    transpose W_p  (8 nblk x 128 kblk = 1024)  -> g_Wph/g_Wpl
//   [19456, 19968)    split codebook (512)                       -> g_Ch/g_Cl
//   [19968, 19972)    counts/loss zero + codebook norms
//   [19972, 20004)    g_best init
#define PRE_BLOCKS 20004

__global__ void k_pre(const float* __restrict__ states,
                      const float* __restrict__ next_states,
                      const float* __restrict__ W_s,
                      const float* __restrict__ W_p,
                      const float* __restrict__ cb) {
    const int b = blockIdx.x;
    const int tid = threadIdx.x;

    if (b < 16384) {
        // float4 split: 8192 blocks per input
        const int which = b >> 13;
        const int bb = b & 8191;
        const float* src = which ? next_states : states;
        const uint32_t woff = which ? (uint32_t)(NROWS * DDIM / 2) : 0u;
        int i = bb * 256 + tid;                      // float4 index
        float4 v = ((const float4*)src)[i];
        uint16_t h0, l0, h1, l1, h2, l2, h3, l3;
        split_h(v.x, h0, l0);
        split_h(v.y, h1, l1);
        split_h(v.z, h2, l2);
        split_h(v.w, h3, l3);
        uint2 hp, lp;
        hp.x = (uint32_t)h0 | ((uint32_t)h1 << 16);
        hp.y = (uint32_t)h2 | ((uint32_t)h3 << 16);
        lp.x = (uint32_t)l0 | ((uint32_t)l1 << 16);
        lp.y = (uint32_t)l2 | ((uint32_t)l3 << 16);
        *(uint2*)(g_Sh + woff + 2 * i) = hp;
        *(uint2*)(g_Sl + woff + 2 * i) = lp;
    } else if (b < 19456) {
        const int which = (b >= 18432);              // 0 = W_s, 1 = W_p
        const int bb = which ? (b - 18432) : (b - 16384);
        const int K = which ? (2 * EDIM) : DDIM;
        const int N = which ? CDDIM : EDIM;
        const int nblk = N / 32;
        const int n0 = (bb % nblk) * 32, k0 = (bb / nblk) * 32;
        const float* src = which ? W_p : W_s;
        __half* dh = (__half*)(which ? g_Wph : g_Wsh);
        __half* dl = (__half*)(which ? g_Wpl : g_Wsl);

        __shared__ float ts[32][33];
        const int tx = tid & 31, ty = tid >> 5;
        #pragma unroll
        for (int r = 0; r < 4; r++)
            ts[ty + 8 * r][tx] = src[(size_t)(k0 + ty + 8 * r) * N + n0 + tx];
        __syncthreads();
        #pragma unroll
        for (int r = 0; r < 4; r++) {
            int n = n0 + ty + 8 * r, k = k0 + tx;
            float v = ts[tx][ty + 8 * r];
            uint16_t h, l;
            split_h(v, h, l);
            dh[(size_t)n * K + k] = __ushort_as_half(h);
            dl[(size_t)n * K + k] = __ushort_as_half(l);
        }
    } else if (b < 19968) {
        int i = (b - 19456) * 256 + tid;
        float2 v = ((const float2*)cb)[i];
        uint16_t h0, l0, h1, l1;
        split_h(v.x, h0, l0);
        split_h(v.y, h1, l1);
        g_Ch[i] = (uint32_t)h0 | ((uint32_t)h1 << 16);
        g_Cl[i] = (uint32_t)l0 | ((uint32_t)l1 << 16);
    } else if (b < 19972) {
        int c = (b - 19968) * 256 + tid;
        if (c < NCODE) {
            g_counts[c] = 0;
            float s = 0.0f;
            const float* row = cb + (size_t)c * CDDIM;
            #pragma unroll 8
            for (int k = 0; k < CDDIM; k++) { float v = row[k]; s += v * v; }
            g_cnorm[c] = s;
        }
        if (c == 0) g_loss_sum = 0.0f;
    } else {
        int r = (b - 19972) * 256 + tid;
        if (r < NROWS) g_best[r] = 0xFFFFFFFFFFFFFFFFull;
    }
}

// ---------------- MID-tile fp16 split GEMM (enc + score) ----------------
// CTA 128(M) x 128(N), 8 warps 2m x 4n, warp tile 64x32, NSTG=3, 2 CTAs/SM.
// MODE 0: H = gelu(S @ Ws^T + b_s) -> g_Hh/g_Hl  (z via blockIdx.z)
// MODE 2: scores = latent . CB^T   -> packed atomicMin argmin
template <int MODE, int KT>
__global__ void __launch_bounds__(256, 2) gemm_mid(const float* __restrict__ bias) {
    extern __shared__ uint32_t smu[];
    constexpr int KW   = KT / 2;
    constexpr int NCH  = KT / 32;
    constexpr int ASZ  = 128 * 32;            // words
    constexpr int BSZ  = 128 * 32;
    constexpr int STG  = ASZ + BSZ;           // 8192 words = 32KB
    constexpr int NSTG = 3;

    const uint32_t* Ah = (MODE == 0) ? g_Sh : g_Lh;
    const uint32_t* Al = (MODE == 0) ? g_Sl : g_Ll;
    const uint32_t* Bh = (MODE == 0) ? g_Wsh : g_Ch;
    const uint32_t* Bl = (MODE == 0) ? g_Wsl : g_Cl;

    const int tid = threadIdx.x;
    const int wid = tid >> 5, lane = tid & 31;
    const int wm  = (wid & 1) * 64;
    const int wn  = (wid >> 1) * 32;
    const int lt  = lane & 3, lg = lane >> 2;

    const int m0 = blockIdx.y * 128, n0 = blockIdx.x * 128;
    const size_t arow0 = (MODE == 0) ? ((size_t)blockIdx.z * NROWS + m0) : (size_t)m0;
    const uint32_t sb = smem_u32(smu);

    const int l7 = lane & 7;
    const int amrow0 = wm + l7 + 8 * ((lane >> 3) & 1);      // + 16*mt
    const uint32_t axk = ((lane >> 4) & 1) ^ l7;
    const int bnrow0 = wn + l7 + 8 * ((lane >> 4) & 1);      // + 16*p
    const uint32_t bxk = ((lane >> 3) & 1) ^ l7;

    float acc[4][4][4];
    #pragma unroll
    for (int i = 0; i < 4; i++)
        #pragma unroll
        for (int j = 0; j < 4; j++)
            #pragma unroll
            for (int e = 0; e < 4; e++) acc[i][j][e] = 0.0f;

    auto copy_chunk = [&](int c, int stg) {
        const uint32_t dA = sb + stg * STG * 4;
        const uint32_t dB = dA + ASZ * 4;
        #pragma unroll
        for (int j = 0; j < 4; j++) {
            int u = tid + j * 256;
            int m = u >> 3, p = u & 7;
            const uint32_t* s = ((p < 4) ? Ah : Al)
                + (arow0 + m) * KW + c * 16 + (p & 3) * 4;
            uint32_t dst = dA + (m * 32 + ((p ^ (m & 7)) << 2)) * 4;
            CP16(dst, s);
        }
        #pragma unroll
        for (int j = 0; j < 4; j++) {
            int u = tid + j * 256;
            int n = u >> 3, p = u & 7;
            const uint32_t* s = ((p < 4) ? Bh : Bl)
                + (size_t)(n0 + n) * KW + c * 16 + (p & 3) * 4;
            uint32_t dst = dB + (n * 32 + ((p ^ (n & 7)) << 2)) * 4;
            CP16(dst, s);
        }
    };

    auto compute = [&](int stg) {
        const uint32_t sA = sb + stg * STG * 4;
        const uint32_t sB = sA + ASZ * 4;
        #pragma unroll
        for (int s = 0; s < 2; s++) {
            const uint32_t ch = 2 * s;
            const uint32_t cl = 2 * s + 4;
            uint32_t bh[2][4], bl[2][4];
            #pragma unroll
            for (int p = 0; p < 2; p++) {
                const uint32_t bb = sB + (bnrow0 + 16 * p) * 128;
                ldm_x4(bh[p], bb + ((ch ^ bxk) << 4));
                ldm_x4(bl[p], bb + ((cl ^ bxk) << 4));
            }
            #pragma unroll
            for (int mt = 0; mt < 4; mt++) {
                uint32_t ah[4], al[4];
                const uint32_t ab = sA + (amrow0 + 16 * mt) * 128;
                ldm_x4(ah, ab + ((ch ^ axk) << 4));
                ldm_x4(al, ab + ((cl ^ axk) << 4));
                // hh
                mma16(acc[mt][0], ah, bh[0]);
                mma16(acc[mt][1], ah, bh[0] + 2);
                mma16(acc[mt][2], ah, bh[1]);
                mma16(acc[mt][3], ah, bh[1] + 2);
                // hl
                mma16(acc[mt][0], ah, bl[0]);
                mma16(acc[mt][1], ah, bl[0] + 2);
                mma16(acc[mt][2], ah, bl[1]);
                mma16(acc[mt][3], ah, bl[1] + 2);
                // lh
                mma16(acc[mt][0], al, bh[0]);
                mma16(acc[mt][1], al, bh[0] + 2);
                mma16(acc[mt][2], al, bh[1]);
                mma16(acc[mt][3], al, bh[1] + 2);
            }
        }
    };

    // ---- prologue ----
    #pragma unroll
    for (int c = 0; c < NSTG - 1 && c < NCH; c++) { copy_chunk(c, c); CP_COMMIT(); }

    // ---- mainloop ----
    int stg_c = 0, stg_n = NSTG - 1;
    for (int c = 0; c < NCH; c++) {
        cp_wait<NSTG - 2>();
        __syncthreads();
        const int cn = c + NSTG - 1;
        if (cn < NCH) copy_chunk(cn, stg_n);
        CP_COMMIT();
        compute(stg_c);
        stg_c = (stg_c + 1 == NSTG) ? 0 : stg_c + 1;
        stg_n = (stg_n + 1 == NSTG) ? 0 : stg_n + 1;
    }

    // ---- epilogue ----
    if (MODE == 0) {
        const int zoff = blockIdx.z ? EDIM : 0;
        #pragma unroll
        for (int mt = 0; mt < 4; mt++)
            #pragma unroll
            for (int h = 0; h < 2; h++) {
                const int row = m0 + wm + mt * 16 + lg + h * 8;
                #pragma unroll
                for (int nt = 0; nt < 4; nt++) {
                    const int col = wn + nt * 8 + 2 * lt;
                    float g0 = gelu_tanh(acc[mt][nt][h * 2 + 0] + bias[n0 + col]);
                    float g1 = gelu_tanh(acc[mt][nt][h * 2 + 1] + bias[n0 + col + 1]);
                    uint16_t h0, l0, h1, l1;
                    split_h(g0, h0, l0);
                    split_h(g1, h1, l1);
                    size_t cw = (size_t)row * (2 * EDIM / 2) + ((zoff + n0 + col) >> 1);
                    g_Hh[cw] = (uint32_t)h0 | ((uint32_t)h1 << 16);
                    g_Hl[cw] = (uint32_t)l0 | ((uint32_t)l1 << 16);
                }
            }
    } else {
        #pragma unroll
        for (int mt = 0; mt < 4; mt++)
            #pragma unroll
            for (int h = 0; h < 2; h++) {
                const int row = m0 + wm + mt * 16 + lg + h * 8;
                float best = INFINITY; int bi = 0;
                #pragma unroll
                for (int nt = 0; nt < 4; nt++)
                    #pragma unroll
                    for (int e = 0; e < 2; e++) {
                        const int col = n0 + wn + nt * 8 + 2 * lt + e;
                        float s = g_cnorm[col] - 2.0f * acc[mt][nt][h * 2 + e];
                        if (s < best) { best = s; bi = col; }
                    }
                #pragma unroll
                for (int msk = 1; msk <= 2; msk <<= 1) {
                    float ov = __shfl_xor_sync(0xffffffffu, best, msk);
                    int   oi = __shfl_xor_sync(0xffffffffu, bi,   msk);
                    if (ov < best || (ov == best && oi < bi)) { best = ov; bi = oi; }
                }
                if (lt == 0) {
                    unsigned long long key =
                        ((unsigned long long)ford(best) << 32) | (unsigned)bi;
                    atomicMin(&g_best[row], key);
                }
            }
    }
}

// ---------------- pol GEMM ----------------
// latent(fp16 h/l only) = H @ Wp^T + b_p
// CTA 64x128, 8 warps 2m x 4n, warp 32x32, NSTG=4, 2 CTAs/SM.
__global__ void __launch_bounds__(256, 2) gemm_pol(const float* __restrict__ bias) {
    extern __shared__ uint32_t smu[];
    constexpr int KT   = 2 * EDIM;
    constexpr int KW   = KT / 2;
    constexpr int NCH  = KT / 32;
    constexpr int ASZ  = 64 * 32;
    constexpr int BSZ  = 128 * 32;
    constexpr int STG  = ASZ + BSZ;
    constexpr int NSTG = 4;

    const int tid = threadIdx.x;
    const int wid = tid >> 5, lane = tid & 31;
    const int wm  = (wid & 1) * 32;
    const int wn  = (wid >> 1) * 32;
    const int lt  = lane & 3, lg = lane >> 2;

    const int m0 = blockIdx.y * 64, n0 = blockIdx.x * 128;
    const uint32_t sb = smem_u32(smu);

    const int l7 = lane & 7;
    const int amrow0 = wm + l7 + 8 * ((lane >> 3) & 1);
    const uint32_t axk = ((lane >> 4) & 1) ^ l7;
    const int bnrow0 = wn + l7 + 8 * ((lane >> 4) & 1);
    const uint32_t bxk = ((lane >> 3) & 1) ^ l7;

    float acc[2][4][4];
    #pragma unroll
    for (int i = 0; i < 2; i++)
        #pragma unroll
        for (int j = 0; j < 4; j++)
            #pragma unroll
            for (int e = 0; e < 4; e++) acc[i][j][e] = 0.0f;

    auto copy_chunk = [&](int c, int stg) {
        const uint32_t dA = sb + stg * STG * 4;
        const uint32_t dB = dA + ASZ * 4;
        #pragma unroll
        for (int j = 0; j < 2; j++) {
            int u = tid + j * 256;
            int m = u >> 3, p = u & 7;
            const uint32_t* s = ((p < 4) ? g_Hh : g_Hl)
                + (size_t)(m0 + m) * KW + c * 16 + (p & 3) * 4;
            uint32_t dst = dA + (m * 32 + ((p ^ (m & 7)) << 2)) * 4;
            CP16(dst, s);
        }
        #pragma unroll
        for (int j = 0; j < 4; j++) {
            int u = tid + j * 256;
            int n = u >> 3, p = u & 7;
            const uint32_t* s = ((p < 4) ? g_Wph : g_Wpl)
                + (size_t)(n0 + n) * KW + c * 16 + (p & 3) * 4;
            uint32_t dst = dB + (n * 32 + ((p ^ (n & 7)) << 2)) * 4;
            CP16(dst, s);
        }
    };

    auto compute = [&](int stg) {
        const uint32_t sA = sb + stg * STG * 4;
        const uint32_t sB = sA + ASZ * 4;
        const uint32_t aBase0 = sA + (amrow0)      * 128;
        const uint32_t aBase1 = sA + (amrow0 + 16) * 128;
        #pragma unroll
        for (int s = 0; s < 2; s++) {
            const uint32_t ch = 2 * s;
            const uint32_t cl = 2 * s + 4;
            uint32_t ah[2][4], al[2][4];
            ldm_x4(ah[0], aBase0 + ((ch ^ axk) << 4));
            ldm_x4(al[0], aBase0 + ((cl ^ axk) << 4));
            ldm_x4(ah[1], aBase1 + ((ch ^ axk) << 4));
            ldm_x4(al[1], aBase1 + ((cl ^ axk) << 4));
            #pragma unroll
            for (int p = 0; p < 2; p++) {
                uint32_t bh[4], bl[4];
                const uint32_t bb = sB + (bnrow0 + 16 * p) * 128;
                ldm_x4(bh, bb + ((ch ^ bxk) << 4));
                ldm_x4(bl, bb + ((cl ^ bxk) << 4));
                mma16(acc[0][2 * p],     ah[0], bh);
                mma16(acc[0][2 * p + 1], ah[0], bh + 2);
                mma16(acc[1][2 * p],     ah[1], bh);
                mma16(acc[1][2 * p + 1], ah[1], bh + 2);
                mma16(acc[0][2 * p],     ah[0], bl);
                mma16(acc[0][2 * p + 1], ah[0], bl + 2);
                mma16(acc[1][2 * p],     ah[1], bl);
                mma16(acc[1][2 * p + 1], ah[1], bl + 2);
                mma16(acc[0][2 * p],     al[0], bh);
                mma16(acc[0][2 * p + 1], al[0], bh + 2);
                mma16(acc[1][2 * p],     al[1], bh);
                mma16(acc[1][2 * p + 1], al[1], bh + 2);
            }
        }
    };

    #pragma unroll
    for (int c = 0; c < NSTG - 1 && c < NCH; c++) { copy_chunk(c, c); CP_COMMIT(); }
    for (int c = 0; c < NCH; c++) {
        cp_wait<NSTG - 2>();
        __syncthreads();
        const int cn = c + NSTG - 1;
        if (cn < NCH) copy_chunk(cn, cn & (NSTG - 1));
        CP_COMMIT();
        compute(c & (NSTG - 1));
    }

    #pragma unroll
    for (int mt = 0; mt < 2; mt++)
        #pragma unroll
        for (int h = 0; h < 2; h++) {
            const int row = m0 + wm + mt * 16 + lg + h * 8;
            #pragma unroll
            for (int nt = 0; nt < 4; nt++) {
                const int col = wn + nt * 8 + 2 * lt;
                float v0 = acc[mt][nt][h * 2 + 0] + bias[n0 + col];
                float v1 = acc[mt][nt][h * 2 + 1] + bias[n0 + col + 1];
                uint16_t h0, l0, h1, l1;
                split_h(v0, h0, l0);
                split_h(v1, h1, l1);
                size_t cw = (size_t)row * (CDDIM / 2) + ((n0 + col) >> 1);
                g_Lh[cw] = (uint32_t)h0 | ((uint32_t)h1 << 16);
                g_Ll[cw] = (uint32_t)l0 | ((uint32_t)l1 << 16);
            }
        }
}

// ---------------- finalize ----------------
__global__ __launch_bounds__(256) void k_final(const float* __restrict__ CB,
                                               float* __restrict__ out, int full) {
    const int warp = threadIdx.x >> 5, lane = threadIdx.x & 31;
    const int row = blockIdx.x * 8 + warp;

    const int idx = (int)(unsigned)(g_best[row] & 0xffffffffull);

    // quantize output + commitment-loss partial (latent reconstructed h+l)
    float ls = 0.0f;
    #pragma unroll
    for (int it = 0; it < 4; it++) {
        int jw = it * 32 + lane;                       // u32 word index (0..127)
        uint32_t hw = g_Lh[(size_t)row * (CDDIM / 2) + jw];
        uint32_t lw = g_Ll[(size_t)row * (CDDIM / 2) + jw];
        float l0 = __half2float(__ushort_as_half((uint16_t)(hw & 0xffff)))
                 + __half2float(__ushort_as_half((uint16_t)(lw & 0xffff)));
        float l1 = __half2float(__ushort_as_half((uint16_t)(hw >> 16)))
                 + __half2float(__ushort_as_half((uint16_t)(lw >> 16)));
        float2 c = *(const float2*)(CB + (size_t)idx * CDDIM + 2 * jw);
        *(float2*)(out + OFF_Q + (size_t)row * CDDIM + 2 * jw) = c;
        float d0 = c.x - l0, d1 = c.y - l1;
        ls += d0 * d0 + d1 * d1;
    }
    #pragma unroll
    for (int off = 16; off > 0; off >>= 1)
        ls += __shfl_down_sync(0xffffffffu, ls, off);
    if (lane == 0) {
        atomicAdd(&g_loss_sum, ls);
        atomicAdd(&g_counts[idx], 1);
    }
    if (full) {
        // one-hot encodings, float2 stores (OFF_ENC is 8B-aligned)
        float* enc = out + OFF_ENC + (size_t)row * NCODE;
        const int iw = idx >> 1;                       // float2 word holding idx
        #pragma unroll
        for (int it = 0; it < 16; it++) {
            int jw = it * 32 + lane;                   // float2 index (0..511)
            float2 z;
            z.x = 0.0f; z.y = 0.0f;
            if (jw == iw) { if (idx & 1) z.y = 1.0f; else z.x = 1.0f; }
            *(float2*)(enc + 2 * jw) = z;
        }
        if (lane == 0) out[OFF_IDX + row] = (float)idx;
    }
}

__global__ void k_scalar(float* __restrict__ out) {
    __shared__ float sh[256];
    int t = threadIdx.x;
    float e = 0.0f;
    for (int c = t; c < NCODE; c += 256) {
        float p = (float)g_counts[c] * (1.0f / (float)NROWS);
        e += p * logf(p + 1e-10f);
    }
    sh[t] = e;
    __syncthreads();
    for (int s = 128; s > 0; s >>= 1) {
        if (t < s) sh[t] += sh[t + s];
        __syncthreads();
    }
    if (t == 0) {
        out[OFF_LOSS] = 0.25f * g_loss_sum / ((float)NROWS * (float)CDDIM);
        out[OFF_PERP] = expf(-sh[0]);
    }
}

// ---------------- launch ----------------
extern "C" void kernel_launch(void* const* d_in, const int* in_sizes, int n_in,
                              void* d_out, int out_size) {
    const float* states      = (const float*)d_in[0];
    const float* next_states = (const float*)d_in[1];
    const float* W_s         = (const float*)d_in[2];
    const float* b_s         = (const float*)d_in[3];
    const float* W_p         = (const float*)d_in[4];
    const float* b_p         = (const float*)d_in[5];
    const float* codebook    = (const float*)d_in[6];
    float* out = (float*)d_out;
    int full = (out_size >= OFF_ENC) ? 1 : 0;

    constexpr int SM_MID = 3 * (128 * 32 + 128 * 32) * 4;    // 98304
    constexpr int SM_POL = 4 * (64 * 32 + 128 * 32) * 4;     // 98304
    cudaFuncSetAttribute(gemm_mid<0, DDIM>,
                         cudaFuncAttributeMaxDynamicSharedMemorySize, SM_MID);
    cudaFuncSetAttribute(gemm_mid<2, CDDIM>,
                         cudaFuncAttributeMaxDynamicSharedMemorySize, SM_MID);
    cudaFuncSetAttribute(gemm_pol,
                         cudaFuncAttributeMaxDynamicSharedMemorySize, SM_POL);

    k_pre<<<PRE_BLOCKS, 256>>>(states, next_states, W_s, W_p, codebook);

    // encoder: M=8192, N=2048, K=1024 (two inputs via grid.z) -> Hh/Hl
    gemm_mid<0, DDIM><<<dim3(EDIM / 128, NROWS / 128, 2), 256, SM_MID>>>(b_s);
    // policy head: M=8192, N=256, K=4096 -> latent fp16 h/l
    gemm_pol<<<dim3(CDDIM / 128, NROWS / 64, 1), 256, SM_POL>>>(b_p);
    // scores: M=8192, N=1024 codes, K=256 -> packed argmin
    gemm_mid<2, CDDIM><<<dim3(NCODE / 128, NROWS / 128, 1), 256, SM_MID>>>(nullptr);

    k_final<<<NROWS / 8, 256>>>(codebook, out, full);
    if (full) k_scalar<<<1, 256>>>(out);
}